// round 15
// baseline (speedup 1.0000x reference)
#include <cuda_runtime.h>
#include <cuda_bf16.h>

#define NQ     4096
#define MT     16384
#define DD     32
#define OUTD   16
#define KNB    5
#define EPSV   1e-6f

#define NCH    256             // 64-pt chunks per query (64 bits per mask)
#define CHPT   64              // points per chunk
#define NSUB   8               // threshold subsets (64 pts each, first 512 pts)
#define MARG   4.0f            // bf16 screen margin (rms err ~0.05; huge headroom)

typedef unsigned long long u64;
typedef unsigned int u32;

// ---- device globals ----
__device__ u64   g_tp[MT * 16];                     // scaled points fp32 d-pairs (2MB)
__device__ float g_tnf[MT];                         // point norms (fp32, exact)
__device__ u64   g_qd[NQ * 16];                     // scaled queries fp32 d-pairs
__device__ float g_qn[NQ];                          // query norms
__device__ u32   g_tbw[MT * 16];                    // scaled points bf16 pairs (1MB)
__device__ u32   g_qbw[NQ * 16];                    // scaled queries bf16 pairs
__device__ float g_s5[NQ * NSUB * KNB];             // per-subset top-5 values
__device__ float g_T[NQ];                           // exact 5th of first 512
__device__ u64   g_mask[(size_t)NQ * NCH];          // candidate bitmasks (8MB)

// ---- scalar helpers ----
__device__ __forceinline__ u64 fma2(u64 a, u64 b, u64 c) {
    u64 d;
    asm("fma.rn.f32x2 %0, %1, %2, %3;" : "=l"(d) : "l"(a), "l"(b), "l"(c));
    return d;
}
__device__ __forceinline__ u64 pack2(float lo, float hi) {
    return ((u64)__float_as_uint(hi) << 32) | (u64)__float_as_uint(lo);
}
__device__ __forceinline__ float lo32(u64 v) { return __uint_as_float((u32)v); }
__device__ __forceinline__ float hi32(u64 v) { return __uint_as_float((u32)(v >> 32)); }
__device__ __forceinline__ u32 bf2u(float a, float b) {
    __nv_bfloat162 h = __floats2bfloat162_rn(a, b);   // low half = a (dim k), high = b (k+1)
    return *(u32*)&h;
}

#define NET5(V, s) do {                          \
    V[4] = fminf(fmaxf((s), V[3]), V[4]);        \
    V[3] = fminf(fmaxf((s), V[2]), V[3]);        \
    V[2] = fminf(fmaxf((s), V[1]), V[2]);        \
    V[1] = fminf(fmaxf((s), V[0]), V[1]);        \
    V[0] = fminf((s), V[0]);                     \
} while (0)

// exact fp32 dot->distance (thresh + final; margin covers the bf16 screen)
__device__ __forceinline__ float point_dist(const u64* __restrict__ prow,
                                            const u64* qd, float nrm) {
    u64 acc = 0;
    #pragma unroll
    for (int i = 0; i < 8; i++) {
        ulonglong2 P = *(const ulonglong2*)(prow + 2 * i);
        acc = fma2(qd[2 * i],     P.x, acc);
        acc = fma2(qd[2 * i + 1], P.y, acc);
    }
    float dot = lo32(acc) + hi32(acc);
    return fmaf(dot, -2.0f, nrm);
}

__device__ __forceinline__ void load_qd(u64* qd, int q) {
    const ulonglong2* qp = (const ulonglong2*)(g_qd + (size_t)q * 16);
    #pragma unroll
    for (int i = 0; i < 8; i++) {
        ulonglong2 v = qp[i];
        qd[2 * i] = v.x; qd[2 * i + 1] = v.y;
    }
}

// m16n8k16 bf16 MMA (base PTX feature, compiles for plain sm_103)
__device__ __forceinline__ void mma_bf16(float& d0, float& d1, float& d2, float& d3,
                                         u32 a0, u32 a1, u32 a2, u32 a3,
                                         u32 b0, u32 b1) {
    asm volatile(
        "mma.sync.aligned.m16n8k16.row.col.f32.bf16.bf16.f32 "
        "{%0,%1,%2,%3}, {%4,%5,%6,%7}, {%8,%9}, {%0,%1,%2,%3};"
        : "+f"(d0), "+f"(d1), "+f"(d2), "+f"(d3)
        : "r"(a0), "r"(a1), "r"(a2), "r"(a3), "r"(b0), "r"(b1));
}

// ---------------------------------------------------------------------------
// Kernel 0: prep — fp32 d-pair layout + bf16 copies + norms
// ---------------------------------------------------------------------------
__global__ void __launch_bounds__(256) idw_prep(
    const float* __restrict__ xg, const float* __restrict__ txg,
    const float* __restrict__ wg)
{
    __shared__ float sinv[DD];
    const int tid = threadIdx.x;
    if (tid < DD) sinv[tid] = expf(-wg[tid]);
    __syncthreads();

    const int gid = blockIdx.x;
    if (gid < 64) {
        const int p = gid * 256 + tid;          // point 0..16383
        const float4* pr = (const float4*)(txg + (size_t)p * DD);
        float n = 0.f;
        #pragma unroll
        for (int i = 0; i < 8; i++) {
            float4 v = pr[i];
            float f0 = v.x * sinv[4 * i + 0];
            float f1 = v.y * sinv[4 * i + 1];
            float f2 = v.z * sinv[4 * i + 2];
            float f3 = v.w * sinv[4 * i + 3];
            g_tp[(size_t)p * 16 + 2 * i + 0] = pack2(f0, f1);
            g_tp[(size_t)p * 16 + 2 * i + 1] = pack2(f2, f3);
            g_tbw[(size_t)p * 16 + 2 * i + 0] = bf2u(f0, f1);
            g_tbw[(size_t)p * 16 + 2 * i + 1] = bf2u(f2, f3);
            n = fmaf(f0, f0, fmaf(f1, f1, fmaf(f2, f2, fmaf(f3, f3, n))));
        }
        g_tnf[p] = n;
    } else {
        const int q = (gid - 64) * 256 + tid;   // query 0..4095
        const float4* xr = (const float4*)(xg + (size_t)q * DD);
        float qn = 0.f;
        #pragma unroll
        for (int i = 0; i < 8; i++) {
            float4 v = xr[i];
            float f0 = v.x * sinv[4 * i + 0];
            float f1 = v.y * sinv[4 * i + 1];
            float f2 = v.z * sinv[4 * i + 2];
            float f3 = v.w * sinv[4 * i + 3];
            g_qd[(size_t)q * 16 + 2 * i + 0] = pack2(f0, f1);
            g_qd[(size_t)q * 16 + 2 * i + 1] = pack2(f2, f3);
            g_qbw[(size_t)q * 16 + 2 * i + 0] = bf2u(f0, f1);
            g_qbw[(size_t)q * 16 + 2 * i + 1] = bf2u(f2, f3);
            qn = fmaf(f0, f0, fmaf(f1, f1, fmaf(f2, f2, fmaf(f3, f3, qn))));
        }
        g_qn[q] = qn;
    }
}

// ---------------------------------------------------------------------------
// Kernel 1: thresh — exact top-5 of one 64-point subset (first 512 pts)
// ---------------------------------------------------------------------------
__global__ void __launch_bounds__(128) idw_thresh()
{
    __shared__ __align__(16) u64   sPt[CHPT * 16];
    __shared__ __align__(16) float sNf[CHPT];

    const int tid = threadIdx.x;
    const int qg  = blockIdx.x >> 3;
    const int sub = blockIdx.x & 7;
    const int q   = qg * 128 + tid;

    {
        const uint4* src = (const uint4*)(g_tp + (size_t)(sub * CHPT) * 16);
        uint4* dst = (uint4*)sPt;
        #pragma unroll
        for (int k = 0; k < 4; k++)
            dst[k * 128 + tid] = src[k * 128 + tid];
        if (tid < 16)
            ((uint4*)sNf)[tid] = ((const uint4*)(g_tnf + sub * CHPT))[tid];
    }

    u64 qd[16];
    load_qd(qd, q);
    __syncthreads();

    float V[KNB] = {3.0e38f, 3.0e38f, 3.0e38f, 3.0e38f, 3.0e38f};
    #pragma unroll 1
    for (int g = 0; g < CHPT / 4; g++) {
        float4 nrm = *(const float4*)&sNf[4 * g];
        float s0 = point_dist(sPt + (4 * g + 0) * 16, qd, nrm.x);
        float s1 = point_dist(sPt + (4 * g + 1) * 16, qd, nrm.y);
        float s2 = point_dist(sPt + (4 * g + 2) * 16, qd, nrm.z);
        float s3 = point_dist(sPt + (4 * g + 3) * 16, qd, nrm.w);
        NET5(V, s0); NET5(V, s1); NET5(V, s2); NET5(V, s3);
    }
    #pragma unroll
    for (int k = 0; k < KNB; k++)
        g_s5[(size_t)q * (NSUB * KNB) + sub * KNB + k] = V[k];
}

// ---------------------------------------------------------------------------
// Kernel 2: mergeT — exact 5th of first 512 points per query
// ---------------------------------------------------------------------------
__global__ void __launch_bounds__(256) idw_mergeT()
{
    const int q = blockIdx.x * 256 + threadIdx.x;
    const float4* src = (const float4*)(g_s5 + (size_t)q * (NSUB * KNB));
    float V[KNB] = {3.0e38f, 3.0e38f, 3.0e38f, 3.0e38f, 3.0e38f};
    #pragma unroll
    for (int i = 0; i < NSUB * KNB / 4; i++) {
        float4 v = src[i];
        NET5(V, v.x); NET5(V, v.y); NET5(V, v.z); NET5(V, v.w);
    }
    g_T[q] = V[4];
}

// ---------------------------------------------------------------------------
// Kernel 3: screen — warp-level bf16 HMMA + margin threshold -> bitmasks
//   Warp: 16 queries x 64-pt tiles via m16n8k16; block: 4 warps = 64 queries.
//   Grid: 64 query-tiles x 8 point-slabs (2048 pts = 32 tiles each).
// ---------------------------------------------------------------------------
__global__ void __launch_bounds__(128) idw_screen()
{
    const unsigned FULL = 0xFFFFFFFFu;
    const int tid = threadIdx.x;
    const int w   = tid >> 5;
    const int l   = tid & 31;
    const int gr  = l >> 2;        // 0..7 (row / B-col group)
    const int c   = l & 3;         // 0..3 (k-pair / C-col group)
    const int qt  = blockIdx.x >> 3;   // 0..63
    const int ps  = blockIdx.x & 7;    // 0..7
    const int q0  = qt * 64 + w * 16 + gr;  // A rows gr and gr+8
    const int q1  = q0 + 8;

    // A fragments for both K=16 steps (fragment map: a0=A[gr][2c..2c+1],
    // a1=A[gr+8][2c..], a2=A[gr][2c+8..], a3=A[gr+8][2c+8..])
    u32 a00 = g_qbw[(size_t)q0 * 16 + c];
    u32 a01 = g_qbw[(size_t)q1 * 16 + c];
    u32 a02 = g_qbw[(size_t)q0 * 16 + c + 4];
    u32 a03 = g_qbw[(size_t)q1 * 16 + c + 4];
    u32 a10 = g_qbw[(size_t)q0 * 16 + c + 8];
    u32 a11 = g_qbw[(size_t)q1 * 16 + c + 8];
    u32 a12 = g_qbw[(size_t)q0 * 16 + c + 12];
    u32 a13 = g_qbw[(size_t)q1 * 16 + c + 12];

    const float Tm0 = g_T[q0] + MARG;
    const float Tm1 = g_T[q1] + MARG;

    #pragma unroll 1
    for (int it = 0; it < 32; it++) {
        const int ch = ps * 32 + it;       // chunk id (64 points)
        const int pb = ch * CHPT;
        u64 mlow = 0, mhigh = 0;

        #pragma unroll
        for (int nt = 0; nt < 8; nt++) {
            // B col = point row (fragment map: b0=B[2c..2c+1][gr], b1=B[2c+8..][gr])
            const size_t prow = (size_t)(pb + 8 * nt + gr) * 16;
            float d0 = 0.f, d1 = 0.f, d2 = 0.f, d3 = 0.f;
            {
                u32 b0 = g_tbw[prow + c];
                u32 b1 = g_tbw[prow + c + 4];
                mma_bf16(d0, d1, d2, d3, a00, a01, a02, a03, b0, b1);
            }
            {
                u32 b0 = g_tbw[prow + c + 8];
                u32 b1 = g_tbw[prow + c + 12];
                mma_bf16(d0, d1, d2, d3, a10, a11, a12, a13, b0, b1);
            }
            // C map: d0,d1 = row q0 cols {2c,2c+1}; d2,d3 = row q1 same cols
            const int p0 = pb + 8 * nt + 2 * c;
            float2 tn = *(const float2*)&g_tnf[p0];
            float s00 = fmaf(d0, -2.0f, tn.x);
            float s01 = fmaf(d1, -2.0f, tn.y);
            float s10 = fmaf(d2, -2.0f, tn.x);
            float s11 = fmaf(d3, -2.0f, tn.y);
            const int sh = 8 * nt + 2 * c;
            mlow  |= ((u64)(s00 <= Tm0) | ((u64)(s01 <= Tm0) << 1)) << sh;
            mhigh |= ((u64)(s10 <= Tm1) | ((u64)(s11 <= Tm1) << 1)) << sh;
        }

        // OR-reduce across the 4 lanes sharing row group gr
        mlow  |= __shfl_xor_sync(FULL, mlow, 1);
        mlow  |= __shfl_xor_sync(FULL, mlow, 2);
        mhigh |= __shfl_xor_sync(FULL, mhigh, 1);
        mhigh |= __shfl_xor_sync(FULL, mhigh, 2);

        if (c == 0) {
            g_mask[(size_t)q0 * NCH + ch] = mlow;
            g_mask[(size_t)q1 * NCH + ch] = mhigh;
        }
    }
}

// ---------------------------------------------------------------------------
// Kernel 4: final — block per query: parallel exact rescue + two-level arg-min
// ---------------------------------------------------------------------------
#define INS5(V, I, s, g) do {                                                  \
    if ((s) < V[4]) {                                                          \
        V[4] = (s); I[4] = (g);                                                \
        if (V[4] < V[3]) { float t_=V[3]; V[3]=V[4]; V[4]=t_; int u_=I[3]; I[3]=I[4]; I[4]=u_; } \
        if (V[3] < V[2]) { float t_=V[2]; V[2]=V[3]; V[3]=t_; int u_=I[2]; I[2]=I[3]; I[3]=u_; } \
        if (V[2] < V[1]) { float t_=V[1]; V[1]=V[2]; V[2]=t_; int u_=I[1]; I[1]=I[2]; I[2]=u_; } \
        if (V[1] < V[0]) { float t_=V[0]; V[0]=V[1]; V[1]=t_; int u_=I[0]; I[0]=I[1]; I[1]=u_; } \
    } } while (0)

__device__ __forceinline__ u32 mono32(float f) {
    u32 b = __float_as_uint(f);
    return b ^ ((u32)((int)b >> 31) | 0x80000000u);
}

__global__ void __launch_bounds__(128) idw_final(
    const float* __restrict__ tyg, float* __restrict__ outg)
{
    __shared__ float sv[4 * KNB];
    __shared__ int   si[4 * KNB];

    const int tid  = threadIdx.x;
    const int lane = tid & 31;
    const int w    = tid >> 5;
    const int q    = blockIdx.x;
    const unsigned FULL = 0xFFFFFFFFu;

    u64 qd[16];
    load_qd(qd, q);

    ulonglong2 mm = *(const ulonglong2*)&g_mask[(size_t)q * NCH + 2 * tid];

    float bv[KNB]; int bi[KNB];
    #pragma unroll
    for (int k = 0; k < KNB; k++) { bv[k] = 3.0e38f; bi[k] = 0; }

    {
        u64 m = mm.x;
        const int pb = (2 * tid) * CHPT;
        while (m) {
            int b = __ffsll((long long)m) - 1;
            m &= m - 1;
            const int idx = pb + b;
            float s = point_dist(g_tp + (size_t)idx * 16, qd, g_tnf[idx]);
            INS5(bv, bi, s, idx);
        }
        m = mm.y;
        const int pb2 = (2 * tid + 1) * CHPT;
        while (m) {
            int b = __ffsll((long long)m) - 1;
            m &= m - 1;
            const int idx = pb2 + b;
            float s = point_dist(g_tp + (size_t)idx * 16, qd, g_tnf[idx]);
            INS5(bv, bi, s, idx);
        }
    }
    __syncwarp(FULL);

    {
        float cur = bv[0]; int curi = bi[0];
        #pragma unroll
        for (int r = 0; r < KNB; r++) {
            u32 key = mono32(cur);
            u32 mn = __reduce_min_sync(FULL, key);
            unsigned msk = __ballot_sync(FULL, key == mn);
            int leader = __ffs(msk) - 1;
            float rv = __shfl_sync(FULL, cur, leader);
            int   ri = __shfl_sync(FULL, curi, leader);
            if (lane == r) { sv[w * KNB + r] = rv; si[w * KNB + r] = ri; }
            if (lane == leader) {
                bv[0]=bv[1]; bi[0]=bi[1];
                bv[1]=bv[2]; bi[1]=bi[2];
                bv[2]=bv[3]; bi[2]=bi[3];
                bv[3]=bv[4]; bi[3]=bi[4];
                bv[4]=3.0e38f; bi[4]=0;
                cur = bv[0]; curi = bi[0];
            }
        }
    }
    __syncthreads();

    if (w == 0) {
        float v  = (lane < 4 * KNB) ? sv[lane] : 3.0e38f;
        int   ix = (lane < 4 * KNB) ? si[lane] : 0;

        float ts[KNB]; int ti[KNB];
        #pragma unroll
        for (int r = 0; r < KNB; r++) {
            u32 key = mono32(v);
            u32 mn = __reduce_min_sync(FULL, key);
            unsigned msk = __ballot_sync(FULL, key == mn);
            int leader = __ffs(msk) - 1;
            ts[r] = __shfl_sync(FULL, v, leader);
            ti[r] = __shfl_sync(FULL, ix, leader);
            if (lane == leader) v = 3.0e38f;
        }

        const float qn = g_qn[q];
        float dv[KNB], wsum = 0.f;
        #pragma unroll
        for (int k = 0; k < KNB; k++) {
            float sq = qn + ts[k];
            dv[k] = rsqrtf(fmaxf(sq, 0.f) + EPSV);
            wsum += dv[k];
        }
        const float wi = 1.f / wsum;

        if (lane < OUTD) {
            float o = 0.f;
            #pragma unroll
            for (int k = 0; k < KNB; k++)
                o = fmaf(dv[k], tyg[(size_t)ti[k] * OUTD + lane], o);
            outg[(size_t)q * OUTD + lane] = o * wi;
        }
    }
}

extern "C" void kernel_launch(void* const* d_in, const int* in_sizes, int n_in,
                              void* d_out, int out_size)
{
    const float *xg = nullptr, *txg = nullptr, *tyg = nullptr, *wg = nullptr;
    for (int i = 0; i < n_in; i++) {
        switch (in_sizes[i]) {
            case NQ * DD:   xg  = (const float*)d_in[i]; break;
            case MT * DD:   txg = (const float*)d_in[i]; break;
            case MT * OUTD: tyg = (const float*)d_in[i]; break;
            case DD:        wg  = (const float*)d_in[i]; break;
        }
    }
    float* outg = (float*)d_out;

    // period-5 sequence: profiled position 4 = screen (HMMA)
    idw_prep  <<< 80, 256 >>>(xg, txg, wg);
    idw_thresh<<< 256, 128 >>>();
    idw_mergeT<<< 16, 256 >>>();
    idw_screen<<< 512, 128 >>>();
    idw_final <<< NQ, 128 >>>(tyg, outg);
}

// round 16
// speedup vs baseline: 1.3774x; 1.3774x over previous
#include <cuda_runtime.h>
#include <cuda_bf16.h>

#define NQ     4096
#define MT     16384
#define DD     32
#define OUTD   16
#define KNB    5
#define EPSV   1e-6f

#define NCH    256             // 64-pt chunks per query (64 bits per mask)
#define CHPT   64              // points per chunk
#define NSUB   8               // threshold subsets (64 pts each, first 512 pts)
#define MARG   4.0f            // bf16 screen margin (rms err ~0.05; huge headroom)
#define BSTR   20              // smem B row stride in u32 (80B, conflict-free)

typedef unsigned long long u64;
typedef unsigned int u32;

// ---- device globals ----
__device__ u64   g_tp[MT * 16];                     // scaled points fp32 d-pairs (2MB)
__device__ float g_tnf[MT];                         // point norms (fp32, exact)
__device__ u64   g_qd[NQ * 16];                     // scaled queries fp32 d-pairs
__device__ float g_qn[NQ];                          // query norms
__device__ u32   g_tbw[MT * 16];                    // scaled points bf16 pairs (1MB)
__device__ u32   g_qbw[NQ * 16];                    // scaled queries bf16 pairs
__device__ float g_s5[NQ * NSUB * KNB];             // per-subset top-5 values
__device__ float g_T[NQ];                           // exact 5th of first 512
__device__ u64   g_mask[(size_t)NQ * NCH];          // candidate bitmasks (8MB)

// ---- scalar helpers ----
__device__ __forceinline__ u64 fma2(u64 a, u64 b, u64 c) {
    u64 d;
    asm("fma.rn.f32x2 %0, %1, %2, %3;" : "=l"(d) : "l"(a), "l"(b), "l"(c));
    return d;
}
__device__ __forceinline__ u64 pack2(float lo, float hi) {
    return ((u64)__float_as_uint(hi) << 32) | (u64)__float_as_uint(lo);
}
__device__ __forceinline__ float lo32(u64 v) { return __uint_as_float((u32)v); }
__device__ __forceinline__ float hi32(u64 v) { return __uint_as_float((u32)(v >> 32)); }
__device__ __forceinline__ u32 bf2u(float a, float b) {
    __nv_bfloat162 h = __floats2bfloat162_rn(a, b);
    return *(u32*)&h;
}

#define NET5(V, s) do {                          \
    V[4] = fminf(fmaxf((s), V[3]), V[4]);        \
    V[3] = fminf(fmaxf((s), V[2]), V[3]);        \
    V[2] = fminf(fmaxf((s), V[1]), V[2]);        \
    V[1] = fminf(fmaxf((s), V[0]), V[1]);        \
    V[0] = fminf((s), V[0]);                     \
} while (0)

// exact fp32 dot->distance (thresh + final; margin covers the bf16 screen)
__device__ __forceinline__ float point_dist(const u64* __restrict__ prow,
                                            const u64* qd, float nrm) {
    u64 acc = 0;
    #pragma unroll
    for (int i = 0; i < 8; i++) {
        ulonglong2 P = *(const ulonglong2*)(prow + 2 * i);
        acc = fma2(qd[2 * i],     P.x, acc);
        acc = fma2(qd[2 * i + 1], P.y, acc);
    }
    float dot = lo32(acc) + hi32(acc);
    return fmaf(dot, -2.0f, nrm);
}

__device__ __forceinline__ void load_qd(u64* qd, int q) {
    const ulonglong2* qp = (const ulonglong2*)(g_qd + (size_t)q * 16);
    #pragma unroll
    for (int i = 0; i < 8; i++) {
        ulonglong2 v = qp[i];
        qd[2 * i] = v.x; qd[2 * i + 1] = v.y;
    }
}

// m16n8k16 bf16 MMA (base PTX feature; validated fragment map in R15)
__device__ __forceinline__ void mma_bf16(float& d0, float& d1, float& d2, float& d3,
                                         u32 a0, u32 a1, u32 a2, u32 a3,
                                         u32 b0, u32 b1) {
    asm volatile(
        "mma.sync.aligned.m16n8k16.row.col.f32.bf16.bf16.f32 "
        "{%0,%1,%2,%3}, {%4,%5,%6,%7}, {%8,%9}, {%0,%1,%2,%3};"
        : "+f"(d0), "+f"(d1), "+f"(d2), "+f"(d3)
        : "r"(a0), "r"(a1), "r"(a2), "r"(a3), "r"(b0), "r"(b1));
}

// ---------------------------------------------------------------------------
// Kernel 0: prep — fp32 d-pair layout + bf16 copies + norms
// ---------------------------------------------------------------------------
__global__ void __launch_bounds__(256) idw_prep(
    const float* __restrict__ xg, const float* __restrict__ txg,
    const float* __restrict__ wg)
{
    __shared__ float sinv[DD];
    const int tid = threadIdx.x;
    if (tid < DD) sinv[tid] = expf(-wg[tid]);
    __syncthreads();

    const int gid = blockIdx.x;
    if (gid < 64) {
        const int p = gid * 256 + tid;          // point 0..16383
        const float4* pr = (const float4*)(txg + (size_t)p * DD);
        float n = 0.f;
        #pragma unroll
        for (int i = 0; i < 8; i++) {
            float4 v = pr[i];
            float f0 = v.x * sinv[4 * i + 0];
            float f1 = v.y * sinv[4 * i + 1];
            float f2 = v.z * sinv[4 * i + 2];
            float f3 = v.w * sinv[4 * i + 3];
            g_tp[(size_t)p * 16 + 2 * i + 0] = pack2(f0, f1);
            g_tp[(size_t)p * 16 + 2 * i + 1] = pack2(f2, f3);
            g_tbw[(size_t)p * 16 + 2 * i + 0] = bf2u(f0, f1);
            g_tbw[(size_t)p * 16 + 2 * i + 1] = bf2u(f2, f3);
            n = fmaf(f0, f0, fmaf(f1, f1, fmaf(f2, f2, fmaf(f3, f3, n))));
        }
        g_tnf[p] = n;
    } else {
        const int q = (gid - 64) * 256 + tid;   // query 0..4095
        const float4* xr = (const float4*)(xg + (size_t)q * DD);
        float qn = 0.f;
        #pragma unroll
        for (int i = 0; i < 8; i++) {
            float4 v = xr[i];
            float f0 = v.x * sinv[4 * i + 0];
            float f1 = v.y * sinv[4 * i + 1];
            float f2 = v.z * sinv[4 * i + 2];
            float f3 = v.w * sinv[4 * i + 3];
            g_qd[(size_t)q * 16 + 2 * i + 0] = pack2(f0, f1);
            g_qd[(size_t)q * 16 + 2 * i + 1] = pack2(f2, f3);
            g_qbw[(size_t)q * 16 + 2 * i + 0] = bf2u(f0, f1);
            g_qbw[(size_t)q * 16 + 2 * i + 1] = bf2u(f2, f3);
            qn = fmaf(f0, f0, fmaf(f1, f1, fmaf(f2, f2, fmaf(f3, f3, qn))));
        }
        g_qn[q] = qn;
    }
}

// ---------------------------------------------------------------------------
// Kernel 1: thresh — exact top-5 of one 64-point subset (first 512 pts)
// ---------------------------------------------------------------------------
__global__ void __launch_bounds__(128) idw_thresh()
{
    __shared__ __align__(16) u64   sPt[CHPT * 16];
    __shared__ __align__(16) float sNf[CHPT];

    const int tid = threadIdx.x;
    const int qg  = blockIdx.x >> 3;
    const int sub = blockIdx.x & 7;
    const int q   = qg * 128 + tid;

    {
        const uint4* src = (const uint4*)(g_tp + (size_t)(sub * CHPT) * 16);
        uint4* dst = (uint4*)sPt;
        #pragma unroll
        for (int k = 0; k < 4; k++)
            dst[k * 128 + tid] = src[k * 128 + tid];
        if (tid < 16)
            ((uint4*)sNf)[tid] = ((const uint4*)(g_tnf + sub * CHPT))[tid];
    }

    u64 qd[16];
    load_qd(qd, q);
    __syncthreads();

    float V[KNB] = {3.0e38f, 3.0e38f, 3.0e38f, 3.0e38f, 3.0e38f};
    #pragma unroll 1
    for (int g = 0; g < CHPT / 4; g++) {
        float4 nrm = *(const float4*)&sNf[4 * g];
        float s0 = point_dist(sPt + (4 * g + 0) * 16, qd, nrm.x);
        float s1 = point_dist(sPt + (4 * g + 1) * 16, qd, nrm.y);
        float s2 = point_dist(sPt + (4 * g + 2) * 16, qd, nrm.z);
        float s3 = point_dist(sPt + (4 * g + 3) * 16, qd, nrm.w);
        NET5(V, s0); NET5(V, s1); NET5(V, s2); NET5(V, s3);
    }
    #pragma unroll
    for (int k = 0; k < KNB; k++)
        g_s5[(size_t)q * (NSUB * KNB) + sub * KNB + k] = V[k];
}

// ---------------------------------------------------------------------------
// Kernel 2: mergeT — exact 5th of first 512 points per query
// ---------------------------------------------------------------------------
__global__ void __launch_bounds__(256) idw_mergeT()
{
    const int q = blockIdx.x * 256 + threadIdx.x;
    const float4* src = (const float4*)(g_s5 + (size_t)q * (NSUB * KNB));
    float V[KNB] = {3.0e38f, 3.0e38f, 3.0e38f, 3.0e38f, 3.0e38f};
    #pragma unroll
    for (int i = 0; i < NSUB * KNB / 4; i++) {
        float4 v = src[i];
        NET5(V, v.x); NET5(V, v.y); NET5(V, v.z); NET5(V, v.w);
    }
    g_T[q] = V[4];
}

// ---------------------------------------------------------------------------
// Kernel 3: screen — smem-staged bf16 HMMA + margin threshold -> bitmasks
//   Block: 4 warps = 64 queries; 8 chunks of 64 points staged in smem.
//   Grid: 64 query-tiles x 32 point-slabs = 2048 blocks.
// ---------------------------------------------------------------------------
__global__ void __launch_bounds__(128) idw_screen()
{
    __shared__ __align__(16) u32  sB[CHPT * BSTR];   // 64 rows x 80B (pad: no conflicts)
    __shared__ float sTn[CHPT];

    const unsigned FULL = 0xFFFFFFFFu;
    const int tid = threadIdx.x;
    const int w   = tid >> 5;
    const int l   = tid & 31;
    const int gr  = l >> 2;        // 0..7 (A row / B col group)
    const int c   = l & 3;         // 0..3 (k-pair / C col group)
    const int qt  = blockIdx.x >> 5;   // 0..63
    const int ps  = blockIdx.x & 31;   // 0..31 (512-pt slab)
    const int q0  = qt * 64 + w * 16 + gr;
    const int q1  = q0 + 8;

    // A fragments for both K=16 steps (R15-validated map)
    u32 a00 = g_qbw[(size_t)q0 * 16 + c];
    u32 a01 = g_qbw[(size_t)q1 * 16 + c];
    u32 a02 = g_qbw[(size_t)q0 * 16 + c + 4];
    u32 a03 = g_qbw[(size_t)q1 * 16 + c + 4];
    u32 a10 = g_qbw[(size_t)q0 * 16 + c + 8];
    u32 a11 = g_qbw[(size_t)q1 * 16 + c + 8];
    u32 a12 = g_qbw[(size_t)q0 * 16 + c + 12];
    u32 a13 = g_qbw[(size_t)q1 * 16 + c + 12];

    const float Tm0 = g_T[q0] + MARG;
    const float Tm1 = g_T[q1] + MARG;

    #pragma unroll 1
    for (int it = 0; it < 8; it++) {
        const int ch = ps * 8 + it;        // chunk id
        const int pb = ch * CHPT;

        __syncthreads();                   // previous chunk fully consumed
        // stage chunk: 64 rows x 16 u32 -> padded rows (2 uint4 per thread)
        {
            const int row = tid >> 1, half = tid & 1;
            const uint4* src = (const uint4*)g_tbw + (size_t)(pb + row) * 4 + half * 2;
            uint4 v0 = src[0];
            uint4 v1 = src[1];
            u32* d = sB + row * BSTR + half * 8;
            *(uint4*)(d)     = v0;
            *(uint4*)(d + 4) = v1;
        }
        if (tid < CHPT) sTn[tid] = g_tnf[pb + tid];
        __syncthreads();

        u64 mlow = 0, mhigh = 0;
        #pragma unroll
        for (int nt = 0; nt < 8; nt++) {
            const u32* br = sB + (8 * nt + gr) * BSTR;
            float d0 = 0.f, d1 = 0.f, d2 = 0.f, d3 = 0.f;
            mma_bf16(d0, d1, d2, d3, a00, a01, a02, a03, br[c],     br[c + 4]);
            mma_bf16(d0, d1, d2, d3, a10, a11, a12, a13, br[c + 8], br[c + 12]);
            // C map: d0,d1 = row q0 cols {2c,2c+1}; d2,d3 = row q1
            const int lc = 8 * nt + 2 * c;
            float2 tn = *(const float2*)&sTn[lc];
            float s00 = fmaf(d0, -2.0f, tn.x);
            float s01 = fmaf(d1, -2.0f, tn.y);
            float s10 = fmaf(d2, -2.0f, tn.x);
            float s11 = fmaf(d3, -2.0f, tn.y);
            mlow  |= ((u64)(s00 <= Tm0) | ((u64)(s01 <= Tm0) << 1)) << lc;
            mhigh |= ((u64)(s10 <= Tm1) | ((u64)(s11 <= Tm1) << 1)) << lc;
        }

        // OR-reduce across the 4 lanes sharing row group gr
        mlow  |= __shfl_xor_sync(FULL, mlow, 1);
        mlow  |= __shfl_xor_sync(FULL, mlow, 2);
        mhigh |= __shfl_xor_sync(FULL, mhigh, 1);
        mhigh |= __shfl_xor_sync(FULL, mhigh, 2);

        if (c == 0) {
            g_mask[(size_t)q0 * NCH + ch] = mlow;
            g_mask[(size_t)q1 * NCH + ch] = mhigh;
        }
    }
}

// ---------------------------------------------------------------------------
// Kernel 4: final — block per query: parallel exact rescue + two-level arg-min
// ---------------------------------------------------------------------------
#define INS5(V, I, s, g) do {                                                  \
    if ((s) < V[4]) {                                                          \
        V[4] = (s); I[4] = (g);                                                \
        if (V[4] < V[3]) { float t_=V[3]; V[3]=V[4]; V[4]=t_; int u_=I[3]; I[3]=I[4]; I[4]=u_; } \
        if (V[3] < V[2]) { float t_=V[2]; V[2]=V[3]; V[3]=t_; int u_=I[2]; I[2]=I[3]; I[3]=u_; } \
        if (V[2] < V[1]) { float t_=V[1]; V[1]=V[2]; V[2]=t_; int u_=I[1]; I[1]=I[2]; I[2]=u_; } \
        if (V[1] < V[0]) { float t_=V[0]; V[0]=V[1]; V[1]=t_; int u_=I[0]; I[0]=I[1]; I[1]=u_; } \
    } } while (0)

__device__ __forceinline__ u32 mono32(float f) {
    u32 b = __float_as_uint(f);
    return b ^ ((u32)((int)b >> 31) | 0x80000000u);
}

__global__ void __launch_bounds__(128) idw_final(
    const float* __restrict__ tyg, float* __restrict__ outg)
{
    __shared__ float sv[4 * KNB];
    __shared__ int   si[4 * KNB];

    const int tid  = threadIdx.x;
    const int lane = tid & 31;
    const int w    = tid >> 5;
    const int q    = blockIdx.x;
    const unsigned FULL = 0xFFFFFFFFu;

    u64 qd[16];
    load_qd(qd, q);

    ulonglong2 mm = *(const ulonglong2*)&g_mask[(size_t)q * NCH + 2 * tid];

    float bv[KNB]; int bi[KNB];
    #pragma unroll
    for (int k = 0; k < KNB; k++) { bv[k] = 3.0e38f; bi[k] = 0; }

    {
        u64 m = mm.x;
        const int pb = (2 * tid) * CHPT;
        while (m) {
            int b = __ffsll((long long)m) - 1;
            m &= m - 1;
            const int idx = pb + b;
            float s = point_dist(g_tp + (size_t)idx * 16, qd, g_tnf[idx]);
            INS5(bv, bi, s, idx);
        }
        m = mm.y;
        const int pb2 = (2 * tid + 1) * CHPT;
        while (m) {
            int b = __ffsll((long long)m) - 1;
            m &= m - 1;
            const int idx = pb2 + b;
            float s = point_dist(g_tp + (size_t)idx * 16, qd, g_tnf[idx]);
            INS5(bv, bi, s, idx);
        }
    }
    __syncwarp(FULL);

    {
        float cur = bv[0]; int curi = bi[0];
        #pragma unroll
        for (int r = 0; r < KNB; r++) {
            u32 key = mono32(cur);
            u32 mn = __reduce_min_sync(FULL, key);
            unsigned msk = __ballot_sync(FULL, key == mn);
            int leader = __ffs(msk) - 1;
            float rv = __shfl_sync(FULL, cur, leader);
            int   ri = __shfl_sync(FULL, curi, leader);
            if (lane == r) { sv[w * KNB + r] = rv; si[w * KNB + r] = ri; }
            if (lane == leader) {
                bv[0]=bv[1]; bi[0]=bi[1];
                bv[1]=bv[2]; bi[1]=bi[2];
                bv[2]=bv[3]; bi[2]=bi[3];
                bv[3]=bv[4]; bi[3]=bi[4];
                bv[4]=3.0e38f; bi[4]=0;
                cur = bv[0]; curi = bi[0];
            }
        }
    }
    __syncthreads();

    if (w == 0) {
        float v  = (lane < 4 * KNB) ? sv[lane] : 3.0e38f;
        int   ix = (lane < 4 * KNB) ? si[lane] : 0;

        float ts[KNB]; int ti[KNB];
        #pragma unroll
        for (int r = 0; r < KNB; r++) {
            u32 key = mono32(v);
            u32 mn = __reduce_min_sync(FULL, key);
            unsigned msk = __ballot_sync(FULL, key == mn);
            int leader = __ffs(msk) - 1;
            ts[r] = __shfl_sync(FULL, v, leader);
            ti[r] = __shfl_sync(FULL, ix, leader);
            if (lane == leader) v = 3.0e38f;
        }

        const float qn = g_qn[q];
        float dv[KNB], wsum = 0.f;
        #pragma unroll
        for (int k = 0; k < KNB; k++) {
            float sq = qn + ts[k];
            dv[k] = rsqrtf(fmaxf(sq, 0.f) + EPSV);
            wsum += dv[k];
        }
        const float wi = 1.f / wsum;

        if (lane < OUTD) {
            float o = 0.f;
            #pragma unroll
            for (int k = 0; k < KNB; k++)
                o = fmaf(dv[k], tyg[(size_t)ti[k] * OUTD + lane], o);
            outg[(size_t)q * OUTD + lane] = o * wi;
        }
    }
}

extern "C" void kernel_launch(void* const* d_in, const int* in_sizes, int n_in,
                              void* d_out, int out_size)
{
    const float *xg = nullptr, *txg = nullptr, *tyg = nullptr, *wg = nullptr;
    for (int i = 0; i < n_in; i++) {
        switch (in_sizes[i]) {
            case NQ * DD:   xg  = (const float*)d_in[i]; break;
            case MT * DD:   txg = (const float*)d_in[i]; break;
            case MT * OUTD: tyg = (const float*)d_in[i]; break;
            case DD:        wg  = (const float*)d_in[i]; break;
        }
    }
    float* outg = (float*)d_out;

    // period-5 sequence: profiled position 4 = screen (HMMA, smem-staged)
    idw_prep  <<< 80, 256 >>>(xg, txg, wg);
    idw_thresh<<< 256, 128 >>>();
    idw_mergeT<<< 16, 256 >>>();
    idw_screen<<< 2048, 128 >>>();
    idw_final <<< NQ, 128 >>>(tyg, outg);
}

// round 17
// speedup vs baseline: 1.8997x; 1.3792x over previous
#include <cuda_runtime.h>
#include <cuda_bf16.h>

#define NQ     4096
#define MT     16384
#define DD     32
#define OUTD   16
#define KNB    5
#define EPSV   1e-6f

#define NCH    256             // 64-pt chunks per query (64 bits per mask)
#define CHPT   64              // points per chunk
#define MARG   2.0f            // >= 2E for bf16 screen (E <~ 0.3 realistic)
#define BSTR   20              // smem B row stride in u32 (80B, conflict-free)

typedef unsigned long long u64;
typedef unsigned int u32;

// ---- device globals ----
__device__ u64   g_tp[MT * 16];                     // scaled points fp32 d-pairs (2MB)
__device__ float g_tnf[MT];                         // point norms (fp32, exact)
__device__ u64   g_qd[NQ * 16];                     // scaled queries fp32 d-pairs
__device__ float g_qn[NQ];                          // query norms
__device__ u32   g_tbw[MT * 16];                    // scaled points bf16 pairs (1MB)
__device__ u32   g_qbw[NQ * 16];                    // scaled queries bf16 pairs
__device__ float g_T[NQ];                           // apx 5th of first 1024 (HMMA)
__device__ u64   g_mask[(size_t)NQ * NCH];          // candidate bitmasks (8MB)

// ---- scalar helpers ----
__device__ __forceinline__ u64 fma2(u64 a, u64 b, u64 c) {
    u64 d;
    asm("fma.rn.f32x2 %0, %1, %2, %3;" : "=l"(d) : "l"(a), "l"(b), "l"(c));
    return d;
}
__device__ __forceinline__ u64 pack2(float lo, float hi) {
    return ((u64)__float_as_uint(hi) << 32) | (u64)__float_as_uint(lo);
}
__device__ __forceinline__ float lo32(u64 v) { return __uint_as_float((u32)v); }
__device__ __forceinline__ float hi32(u64 v) { return __uint_as_float((u32)(v >> 32)); }
__device__ __forceinline__ u32 bf2u(float a, float b) {
    __nv_bfloat162 h = __floats2bfloat162_rn(a, b);
    return *(u32*)&h;
}

#define NET5(V, s) do {                          \
    V[4] = fminf(fmaxf((s), V[3]), V[4]);        \
    V[3] = fminf(fmaxf((s), V[2]), V[3]);        \
    V[2] = fminf(fmaxf((s), V[1]), V[2]);        \
    V[1] = fminf(fmaxf((s), V[0]), V[1]);        \
    V[0] = fminf((s), V[0]);                     \
} while (0)

// exact fp32 dot->distance (final rescue; screen is covered by MARG)
__device__ __forceinline__ float point_dist(const u64* __restrict__ prow,
                                            const u64* qd, float nrm) {
    u64 acc = 0;
    #pragma unroll
    for (int i = 0; i < 8; i++) {
        ulonglong2 P = *(const ulonglong2*)(prow + 2 * i);
        acc = fma2(qd[2 * i],     P.x, acc);
        acc = fma2(qd[2 * i + 1], P.y, acc);
    }
    float dot = lo32(acc) + hi32(acc);
    return fmaf(dot, -2.0f, nrm);
}

__device__ __forceinline__ void load_qd(u64* qd, int q) {
    const ulonglong2* qp = (const ulonglong2*)(g_qd + (size_t)q * 16);
    #pragma unroll
    for (int i = 0; i < 8; i++) {
        ulonglong2 v = qp[i];
        qd[2 * i] = v.x; qd[2 * i + 1] = v.y;
    }
}

// m16n8k16 bf16 MMA (base PTX; fragment map validated in R15/R16)
__device__ __forceinline__ void mma_bf16(float& d0, float& d1, float& d2, float& d3,
                                         u32 a0, u32 a1, u32 a2, u32 a3,
                                         u32 b0, u32 b1) {
    asm volatile(
        "mma.sync.aligned.m16n8k16.row.col.f32.bf16.bf16.f32 "
        "{%0,%1,%2,%3}, {%4,%5,%6,%7}, {%8,%9}, {%0,%1,%2,%3};"
        : "+f"(d0), "+f"(d1), "+f"(d2), "+f"(d3)
        : "r"(a0), "r"(a1), "r"(a2), "r"(a3), "r"(b0), "r"(b1));
}

// ---------------------------------------------------------------------------
// Kernel 0: prep — fp32 d-pair layout + bf16 copies + norms
// ---------------------------------------------------------------------------
__global__ void __launch_bounds__(256) idw_prep(
    const float* __restrict__ xg, const float* __restrict__ txg,
    const float* __restrict__ wg)
{
    __shared__ float sinv[DD];
    const int tid = threadIdx.x;
    if (tid < DD) sinv[tid] = expf(-wg[tid]);
    __syncthreads();

    const int gid = blockIdx.x;
    if (gid < 64) {
        const int p = gid * 256 + tid;          // point 0..16383
        const float4* pr = (const float4*)(txg + (size_t)p * DD);
        float n = 0.f;
        #pragma unroll
        for (int i = 0; i < 8; i++) {
            float4 v = pr[i];
            float f0 = v.x * sinv[4 * i + 0];
            float f1 = v.y * sinv[4 * i + 1];
            float f2 = v.z * sinv[4 * i + 2];
            float f3 = v.w * sinv[4 * i + 3];
            g_tp[(size_t)p * 16 + 2 * i + 0] = pack2(f0, f1);
            g_tp[(size_t)p * 16 + 2 * i + 1] = pack2(f2, f3);
            g_tbw[(size_t)p * 16 + 2 * i + 0] = bf2u(f0, f1);
            g_tbw[(size_t)p * 16 + 2 * i + 1] = bf2u(f2, f3);
            n = fmaf(f0, f0, fmaf(f1, f1, fmaf(f2, f2, fmaf(f3, f3, n))));
        }
        g_tnf[p] = n;
    } else {
        const int q = (gid - 64) * 256 + tid;   // query 0..4095
        const float4* xr = (const float4*)(xg + (size_t)q * DD);
        float qn = 0.f;
        #pragma unroll
        for (int i = 0; i < 8; i++) {
            float4 v = xr[i];
            float f0 = v.x * sinv[4 * i + 0];
            float f1 = v.y * sinv[4 * i + 1];
            float f2 = v.z * sinv[4 * i + 2];
            float f3 = v.w * sinv[4 * i + 3];
            g_qd[(size_t)q * 16 + 2 * i + 0] = pack2(f0, f1);
            g_qd[(size_t)q * 16 + 2 * i + 1] = pack2(f2, f3);
            g_qbw[(size_t)q * 16 + 2 * i + 0] = bf2u(f0, f1);
            g_qbw[(size_t)q * 16 + 2 * i + 1] = bf2u(f2, f3);
            qn = fmaf(f0, f0, fmaf(f1, f1, fmaf(f2, f2, fmaf(f3, f3, qn))));
        }
        g_qn[q] = qn;
    }
}

// ---------------------------------------------------------------------------
// Kernel 1: thrA — HMMA apx top-5 over first 1024 points -> g_T
//   Block: 4 warps = 64 queries. Grid: 64 blocks.
//   Uses the SAME staged-HMMA s_apx computation as the screen.
// ---------------------------------------------------------------------------
__global__ void __launch_bounds__(128) idw_thrA()
{
    __shared__ __align__(16) u32  sB[CHPT * BSTR];
    __shared__ float sTn[CHPT];

    const unsigned FULL = 0xFFFFFFFFu;
    const int tid = threadIdx.x;
    const int w   = tid >> 5;
    const int l   = tid & 31;
    const int gr  = l >> 2;
    const int c   = l & 3;
    const int qt  = blockIdx.x;        // 0..63
    const int q0  = qt * 64 + w * 16 + gr;
    const int q1  = q0 + 8;

    u32 a00 = g_qbw[(size_t)q0 * 16 + c];
    u32 a01 = g_qbw[(size_t)q1 * 16 + c];
    u32 a02 = g_qbw[(size_t)q0 * 16 + c + 4];
    u32 a03 = g_qbw[(size_t)q1 * 16 + c + 4];
    u32 a10 = g_qbw[(size_t)q0 * 16 + c + 8];
    u32 a11 = g_qbw[(size_t)q1 * 16 + c + 8];
    u32 a12 = g_qbw[(size_t)q0 * 16 + c + 12];
    u32 a13 = g_qbw[(size_t)q1 * 16 + c + 12];

    float V0[KNB] = {3.0e38f, 3.0e38f, 3.0e38f, 3.0e38f, 3.0e38f};
    float V1[KNB] = {3.0e38f, 3.0e38f, 3.0e38f, 3.0e38f, 3.0e38f};

    #pragma unroll 1
    for (int ch = 0; ch < 16; ch++) {          // first 1024 points
        const int pb = ch * CHPT;
        __syncthreads();
        {
            const int row = tid >> 1, half = tid & 1;
            const uint4* src = (const uint4*)g_tbw + (size_t)(pb + row) * 4 + half * 2;
            uint4 v0 = src[0];
            uint4 v1 = src[1];
            u32* d = sB + row * BSTR + half * 8;
            *(uint4*)(d)     = v0;
            *(uint4*)(d + 4) = v1;
        }
        if (tid < CHPT) sTn[tid] = g_tnf[pb + tid];
        __syncthreads();

        #pragma unroll
        for (int nt = 0; nt < 8; nt++) {
            const u32* br = sB + (8 * nt + gr) * BSTR;
            float d0 = 0.f, d1 = 0.f, d2 = 0.f, d3 = 0.f;
            mma_bf16(d0, d1, d2, d3, a00, a01, a02, a03, br[c],     br[c + 4]);
            mma_bf16(d0, d1, d2, d3, a10, a11, a12, a13, br[c + 8], br[c + 12]);
            const int lc = 8 * nt + 2 * c;
            float2 tn = *(const float2*)&sTn[lc];
            float s00 = fmaf(d0, -2.0f, tn.x);
            float s01 = fmaf(d1, -2.0f, tn.y);
            float s10 = fmaf(d2, -2.0f, tn.x);
            float s11 = fmaf(d3, -2.0f, tn.y);
            NET5(V0, s00); NET5(V0, s01);
            NET5(V1, s10); NET5(V1, s11);
        }
    }

    // merge top-5 across the 4 c-lanes sharing (w, gr)
    #pragma unroll
    for (int off = 1; off <= 2; off <<= 1) {
        float t0[KNB], t1[KNB];
        #pragma unroll
        for (int k = 0; k < KNB; k++) {
            t0[k] = __shfl_xor_sync(FULL, V0[k], off);
            t1[k] = __shfl_xor_sync(FULL, V1[k], off);
        }
        #pragma unroll
        for (int k = 0; k < KNB; k++) { NET5(V0, t0[k]); NET5(V1, t1[k]); }
    }

    if (c == 0) {
        g_T[q0] = V0[4];
        g_T[q1] = V1[4];
    }
}

// ---------------------------------------------------------------------------
// Kernel 2: screen — smem-staged bf16 HMMA + margin threshold -> bitmasks
//   Grid: 64 query-tiles x 32 point-slabs = 2048 blocks, 8 chunks each.
// ---------------------------------------------------------------------------
__global__ void __launch_bounds__(128) idw_screen()
{
    __shared__ __align__(16) u32  sB[CHPT * BSTR];
    __shared__ float sTn[CHPT];

    const unsigned FULL = 0xFFFFFFFFu;
    const int tid = threadIdx.x;
    const int w   = tid >> 5;
    const int l   = tid & 31;
    const int gr  = l >> 2;
    const int c   = l & 3;
    const int qt  = blockIdx.x >> 5;
    const int ps  = blockIdx.x & 31;
    const int q0  = qt * 64 + w * 16 + gr;
    const int q1  = q0 + 8;

    u32 a00 = g_qbw[(size_t)q0 * 16 + c];
    u32 a01 = g_qbw[(size_t)q1 * 16 + c];
    u32 a02 = g_qbw[(size_t)q0 * 16 + c + 4];
    u32 a03 = g_qbw[(size_t)q1 * 16 + c + 4];
    u32 a10 = g_qbw[(size_t)q0 * 16 + c + 8];
    u32 a11 = g_qbw[(size_t)q1 * 16 + c + 8];
    u32 a12 = g_qbw[(size_t)q0 * 16 + c + 12];
    u32 a13 = g_qbw[(size_t)q1 * 16 + c + 12];

    const float Tm0 = g_T[q0] + MARG;
    const float Tm1 = g_T[q1] + MARG;

    // bit constants: col bits for this lane, pre-shifted per nt-in-half
    const u32 cb0 = 1u << (2 * c);
    const u32 cb1 = 2u << (2 * c);

    #pragma unroll 1
    for (int it = 0; it < 8; it++) {
        const int ch = ps * 8 + it;
        const int pb = ch * CHPT;

        __syncthreads();
        {
            const int row = tid >> 1, half = tid & 1;
            const uint4* src = (const uint4*)g_tbw + (size_t)(pb + row) * 4 + half * 2;
            uint4 v0 = src[0];
            uint4 v1 = src[1];
            u32* d = sB + row * BSTR + half * 8;
            *(uint4*)(d)     = v0;
            *(uint4*)(d + 4) = v1;
        }
        if (tid < CHPT) sTn[tid] = g_tnf[pb + tid];
        __syncthreads();

        u32 m0lo = 0, m0hi = 0, m1lo = 0, m1hi = 0;   // [q0,q1] x [bits 0-31, 32-63]
        #pragma unroll
        for (int nt = 0; nt < 8; nt++) {
            const u32* br = sB + (8 * nt + gr) * BSTR;
            float d0 = 0.f, d1 = 0.f, d2 = 0.f, d3 = 0.f;
            mma_bf16(d0, d1, d2, d3, a00, a01, a02, a03, br[c],     br[c + 4]);
            mma_bf16(d0, d1, d2, d3, a10, a11, a12, a13, br[c + 8], br[c + 12]);
            const int lc = 8 * nt + 2 * c;
            float2 tn = *(const float2*)&sTn[lc];
            float s00 = fmaf(d0, -2.0f, tn.x);
            float s01 = fmaf(d1, -2.0f, tn.y);
            float s10 = fmaf(d2, -2.0f, tn.x);
            float s11 = fmaf(d3, -2.0f, tn.y);
            const int sh = 8 * (nt & 3);               // compile-time per unrolled nt
            const u32 b0 = cb0 << sh, b1 = cb1 << sh;
            if (nt < 4) {
                m0lo |= (s00 <= Tm0) ? b0 : 0u;
                m0lo |= (s01 <= Tm0) ? b1 : 0u;
                m1lo |= (s10 <= Tm1) ? b0 : 0u;
                m1lo |= (s11 <= Tm1) ? b1 : 0u;
            } else {
                m0hi |= (s00 <= Tm0) ? b0 : 0u;
                m0hi |= (s01 <= Tm0) ? b1 : 0u;
                m1hi |= (s10 <= Tm1) ? b0 : 0u;
                m1hi |= (s11 <= Tm1) ? b1 : 0u;
            }
        }

        // OR-reduce across the 4 c-lanes sharing row group gr
        #pragma unroll
        for (int off = 1; off <= 2; off <<= 1) {
            m0lo |= __shfl_xor_sync(FULL, m0lo, off);
            m0hi |= __shfl_xor_sync(FULL, m0hi, off);
            m1lo |= __shfl_xor_sync(FULL, m1lo, off);
            m1hi |= __shfl_xor_sync(FULL, m1hi, off);
        }

        if (c == 0) {
            g_mask[(size_t)q0 * NCH + ch] = (u64)m0lo | ((u64)m0hi << 32);
            g_mask[(size_t)q1 * NCH + ch] = (u64)m1lo | ((u64)m1hi << 32);
        }
    }
}

// ---------------------------------------------------------------------------
// Kernel 3: final — block per query: parallel exact rescue + two-level arg-min
// ---------------------------------------------------------------------------
#define INS5(V, I, s, g) do {                                                  \
    if ((s) < V[4]) {                                                          \
        V[4] = (s); I[4] = (g);                                                \
        if (V[4] < V[3]) { float t_=V[3]; V[3]=V[4]; V[4]=t_; int u_=I[3]; I[3]=I[4]; I[4]=u_; } \
        if (V[3] < V[2]) { float t_=V[2]; V[2]=V[3]; V[3]=t_; int u_=I[2]; I[2]=I[3]; I[3]=u_; } \
        if (V[2] < V[1]) { float t_=V[1]; V[1]=V[2]; V[2]=t_; int u_=I[1]; I[1]=I[2]; I[2]=u_; } \
        if (V[1] < V[0]) { float t_=V[0]; V[0]=V[1]; V[1]=t_; int u_=I[0]; I[0]=I[1]; I[1]=u_; } \
    } } while (0)

__device__ __forceinline__ u32 mono32(float f) {
    u32 b = __float_as_uint(f);
    return b ^ ((u32)((int)b >> 31) | 0x80000000u);
}

__global__ void __launch_bounds__(128) idw_final(
    const float* __restrict__ tyg, float* __restrict__ outg)
{
    __shared__ float sv[4 * KNB];
    __shared__ int   si[4 * KNB];

    const int tid  = threadIdx.x;
    const int lane = tid & 31;
    const int w    = tid >> 5;
    const int q    = blockIdx.x;
    const unsigned FULL = 0xFFFFFFFFu;

    u64 qd[16];
    load_qd(qd, q);

    ulonglong2 mm = *(const ulonglong2*)&g_mask[(size_t)q * NCH + 2 * tid];

    float bv[KNB]; int bi[KNB];
    #pragma unroll
    for (int k = 0; k < KNB; k++) { bv[k] = 3.0e38f; bi[k] = 0; }

    {
        u64 m = mm.x;
        const int pb = (2 * tid) * CHPT;
        while (m) {
            int b = __ffsll((long long)m) - 1;
            m &= m - 1;
            const int idx = pb + b;
            float s = point_dist(g_tp + (size_t)idx * 16, qd, g_tnf[idx]);
            INS5(bv, bi, s, idx);
        }
        m = mm.y;
        const int pb2 = (2 * tid + 1) * CHPT;
        while (m) {
            int b = __ffsll((long long)m) - 1;
            m &= m - 1;
            const int idx = pb2 + b;
            float s = point_dist(g_tp + (size_t)idx * 16, qd, g_tnf[idx]);
            INS5(bv, bi, s, idx);
        }
    }
    __syncwarp(FULL);

    {
        float cur = bv[0]; int curi = bi[0];
        #pragma unroll
        for (int r = 0; r < KNB; r++) {
            u32 key = mono32(cur);
            u32 mn = __reduce_min_sync(FULL, key);
            unsigned msk = __ballot_sync(FULL, key == mn);
            int leader = __ffs(msk) - 1;
            float rv = __shfl_sync(FULL, cur, leader);
            int   ri = __shfl_sync(FULL, curi, leader);
            if (lane == r) { sv[w * KNB + r] = rv; si[w * KNB + r] = ri; }
            if (lane == leader) {
                bv[0]=bv[1]; bi[0]=bi[1];
                bv[1]=bv[2]; bi[1]=bi[2];
                bv[2]=bv[3]; bi[2]=bi[3];
                bv[3]=bv[4]; bi[3]=bi[4];
                bv[4]=3.0e38f; bi[4]=0;
                cur = bv[0]; curi = bi[0];
            }
        }
    }
    __syncthreads();

    if (w == 0) {
        float v  = (lane < 4 * KNB) ? sv[lane] : 3.0e38f;
        int   ix = (lane < 4 * KNB) ? si[lane] : 0;

        float ts[KNB]; int ti[KNB];
        #pragma unroll
        for (int r = 0; r < KNB; r++) {
            u32 key = mono32(v);
            u32 mn = __reduce_min_sync(FULL, key);
            unsigned msk = __ballot_sync(FULL, key == mn);
            int leader = __ffs(msk) - 1;
            ts[r] = __shfl_sync(FULL, v, leader);
            ti[r] = __shfl_sync(FULL, ix, leader);
            if (lane == leader) v = 3.0e38f;
        }

        const float qn = g_qn[q];
        float dv[KNB], wsum = 0.f;
        #pragma unroll
        for (int k = 0; k < KNB; k++) {
            float sq = qn + ts[k];
            dv[k] = rsqrtf(fmaxf(sq, 0.f) + EPSV);
            wsum += dv[k];
        }
        const float wi = 1.f / wsum;

        if (lane < OUTD) {
            float o = 0.f;
            #pragma unroll
            for (int k = 0; k < KNB; k++)
                o = fmaf(dv[k], tyg[(size_t)ti[k] * OUTD + lane], o);
            outg[(size_t)q * OUTD + lane] = o * wi;
        }
    }
}

extern "C" void kernel_launch(void* const* d_in, const int* in_sizes, int n_in,
                              void* d_out, int out_size)
{
    const float *xg = nullptr, *txg = nullptr, *tyg = nullptr, *wg = nullptr;
    for (int i = 0; i < n_in; i++) {
        switch (in_sizes[i]) {
            case NQ * DD:   xg  = (const float*)d_in[i]; break;
            case MT * DD:   txg = (const float*)d_in[i]; break;
            case MT * OUTD: tyg = (const float*)d_in[i]; break;
            case DD:        wg  = (const float*)d_in[i]; break;
        }
    }
    float* outg = (float*)d_out;

    // period-4 sequence: profiled position (5-2)%4=3 -> 4th kernel = FINAL
    idw_prep  <<< 80, 256 >>>(xg, txg, wg);
    idw_thrA  <<< 64, 128 >>>();
    idw_screen<<< 2048, 128 >>>();
    idw_final <<< NQ, 128 >>>(tyg, outg);
}